// round 2
// baseline (speedup 1.0000x reference)
#include <cuda_runtime.h>
#include <cuda_bf16.h>
#include <mma.h>

using namespace nvcuda;

#define NN   50000
#define NE   800000
#define H    128
#define DIN  16
#define DOUT 8
#define NL   4
#define BM   64
#define LDPAD 136
#define NPAD 50048   // 782 * 64

// ---------------- persistent device scratch (no allocs allowed) ----------------
__device__ float g_h[NPAD * H];
__device__ float g_u[NPAD * H];
__device__ float g_v[NPAD * H];
__device__ float g_hsum[NPAD * H];
__device__ int   g_rowptr[NN + 1];
__device__ int   g_tmp[NN];
__device__ int   g_srcs[NE];

__device__ __forceinline__ float gelu_f(float v) {
    return 0.5f * v * (1.0f + erff(v * 0.7071067811865476f));
}

// ---------------- CSR build ----------------
__global__ void k_zero_tmp() {
    int i = blockIdx.x * blockDim.x + threadIdx.x;
    if (i < NN) g_tmp[i] = 0;
}

__global__ void k_count(const int* __restrict__ dst) {
    int e = blockIdx.x * blockDim.x + threadIdx.x;
    if (e < NE) atomicAdd(&g_tmp[dst[e]], 1);
}

__global__ void k_scan() {   // single block, 1024 threads
    __shared__ int s[1024];
    int t = threadIdx.x;
    int carry = 0;
    for (int base = 0; base < NN; base += 1024) {
        int i = base + t;
        int v = (i < NN) ? g_tmp[i] : 0;
        s[t] = v;
        __syncthreads();
        for (int off = 1; off < 1024; off <<= 1) {
            int x = (t >= off) ? s[t - off] : 0;
            __syncthreads();
            s[t] += x;
            __syncthreads();
        }
        if (i < NN) g_rowptr[i] = carry + s[t] - v;
        int tot = s[1023];
        __syncthreads();
        carry += tot;
    }
    if (t == 0) g_rowptr[NN] = carry;
}

__global__ void k_fill(const int* __restrict__ src, const int* __restrict__ dst) {
    int e = blockIdx.x * blockDim.x + threadIdx.x;
    if (e < NE) {
        int d = dst[e];
        int pos = g_rowptr[d] + atomicAdd(&g_tmp[d], 1);
        g_srcs[pos] = src[e];
    }
}

// ---------------- encode: h = MLP2_{16->128->128}(x), SIMT fp32 (exact) ----------------
__global__ void k_encode(const float* __restrict__ x,
                         const float* __restrict__ W1, const float* __restrict__ b1,
                         const float* __restrict__ W2, const float* __restrict__ b2) {
    extern __shared__ float sm[];
    float* W1s = sm;                 // DIN*H
    float* W2s = W1s + DIN * H;      // H*H
    float* hid = W2s + H * H;        // H
    float* xs  = hid + H;            // DIN
    int tid = threadIdx.x;
    for (int i = tid; i < DIN * H; i += 128) W1s[i] = W1[i];
    for (int i = tid; i < H * H;  i += 128) W2s[i] = W2[i];
    float b1r = b1[tid], b2r = b2[tid];
    __syncthreads();
    int n0 = blockIdx.x * 64;
    for (int n = n0; n < n0 + 64; n++) {
        if (tid < DIN) xs[tid] = (n < NN) ? x[n * DIN + tid] : 0.f;
        __syncthreads();
        float a = b1r;
        #pragma unroll
        for (int k = 0; k < DIN; k++) a += xs[k] * W1s[k * H + tid];
        hid[tid] = gelu_f(a);
        __syncthreads();
        float o = b2r;
        #pragma unroll 8
        for (int k = 0; k < H; k++) o += hid[k] * W2s[k * H + tid];
        g_h[n * H + tid] = (n < NN) ? o : 0.f;   // zero padding rows
        __syncthreads();
    }
}

// ---------------- wmma tf32x3 helpers (fp32-accurate via hi/lo split) ----------------
typedef wmma::fragment<wmma::matrix_a, 16, 16, 8, wmma::precision::tf32, wmma::row_major> FragA;
typedef wmma::fragment<wmma::matrix_b, 16, 16, 8, wmma::precision::tf32, wmma::row_major> FragB;
typedef wmma::fragment<wmma::accumulator, 16, 16, 8, float> FragC;

__device__ __forceinline__ void load_A64(float* As, const float* __restrict__ src, int tid) {
    const float4* S4 = (const float4*)src;
    #pragma unroll 4
    for (int i = tid; i < BM * H / 4; i += 256) {
        int r = i >> 5, c4 = i & 31;
        float4 t = S4[i];
        *(float4*)(As + r * LDPAD + c4 * 4) = t;
    }
}

__device__ __forceinline__ void load_B128(float* Bs, const float* __restrict__ W, int tid) {
    const float4* W4 = (const float4*)W;
    #pragma unroll 4
    for (int i = tid; i < H * H / 4; i += 256) {
        int r = i >> 5, c4 = i & 31;
        float4 t = W4[i];
        *(float4*)(Bs + r * LDPAD + c4 * 4) = t;
    }
}

// acc += A @ B with ~fp32 precision: A = a_hi + a_lo, B = b_hi + b_lo (tf32 splits),
// acc += a_hi*b_hi + a_lo*b_hi + a_hi*b_lo   (lo*lo term ~2^-22, dropped)
__device__ __forceinline__ void gemm_tile_acc(FragC (&acc)[4], const float* As,
                                              const float* Bs, int wr, int wc) {
    #pragma unroll
    for (int k = 0; k < H; k += 8) {
        FragA a_hi, a_lo;
        wmma::load_matrix_sync(a_hi, As + wr * 16 * LDPAD + k, LDPAD);
        #pragma unroll
        for (int i = 0; i < a_hi.num_elements; i++) {
            float f  = a_hi.x[i];
            float hi = wmma::__float_to_tf32(f);
            a_lo.x[i] = wmma::__float_to_tf32(f - hi);
            a_hi.x[i] = hi;
        }
        #pragma unroll
        for (int j = 0; j < 4; j++) {
            FragB b_hi, b_lo;
            wmma::load_matrix_sync(b_hi, Bs + k * LDPAD + wc * 64 + j * 16, LDPAD);
            #pragma unroll
            for (int i = 0; i < b_hi.num_elements; i++) {
                float f  = b_hi.x[i];
                float hi = wmma::__float_to_tf32(f);
                b_lo.x[i] = wmma::__float_to_tf32(f - hi);
                b_hi.x[i] = hi;
            }
            wmma::mma_sync(acc[j], a_lo, b_hi, acc[j]);
            wmma::mma_sync(acc[j], a_hi, b_lo, acc[j]);
            wmma::mma_sync(acc[j], a_hi, b_hi, acc[j]);
        }
    }
}

__device__ __forceinline__ void store_tile_s(float* Cs, FragC (&acc)[4], int wr, int wc) {
    #pragma unroll
    for (int j = 0; j < 4; j++)
        wmma::store_matrix_sync(Cs + wr * 16 * LDPAD + wc * 64 + j * 16, acc[j], LDPAD,
                                wmma::mem_row_major);
}

// ---------------- u/v precompute: u = h@W1_top, v = h@W1_bot ----------------
__global__ __launch_bounds__(256) void k_uv(const float* __restrict__ W1) {
    extern __shared__ float sm[];
    float* As = sm;
    float* Bs = As + BM * LDPAD;
    int tid = threadIdx.x, warp = tid >> 5, wr = warp >> 1, wc = warp & 1;
    int row0 = blockIdx.x * BM;
    const float* W = W1 + blockIdx.y * H * H;
    float* out = blockIdx.y ? g_v : g_u;
    load_A64(As, g_h + row0 * H, tid);
    load_B128(Bs, W, tid);
    __syncthreads();
    FragC acc[4];
    #pragma unroll
    for (int j = 0; j < 4; j++) wmma::fill_fragment(acc[j], 0.f);
    gemm_tile_acc(acc, As, Bs, wr, wc);
    #pragma unroll
    for (int j = 0; j < 4; j++)
        wmma::store_matrix_sync(out + (row0 + wr * 16) * H + wc * 64 + j * 16, acc[j], H,
                                wmma::mem_row_major);
}

// ---------------- edge kernel: hsum[n] = sum_{src in seg(n)} gelu(u[src]+v[n]+b1) ----------------
__global__ void k_edge(const float* __restrict__ eb1) {
    int w = (blockIdx.x * blockDim.x + threadIdx.x) >> 5;
    int lane = threadIdx.x & 31;
    if (w >= NN) return;
    float4 vv = ((const float4*)(g_v + (size_t)w * H))[lane];
    float4 bb = ((const float4*)eb1)[lane];
    vv.x += bb.x; vv.y += bb.y; vv.z += bb.z; vv.w += bb.w;
    float4 acc = make_float4(0.f, 0.f, 0.f, 0.f);
    int p1 = g_rowptr[w + 1];
    for (int p = g_rowptr[w]; p < p1; p++) {
        int s = g_srcs[p];
        float4 uu = ((const float4*)(g_u + (size_t)s * H))[lane];
        acc.x += gelu_f(uu.x + vv.x);
        acc.y += gelu_f(uu.y + vv.y);
        acc.z += gelu_f(uu.z + vv.z);
        acc.w += gelu_f(uu.w + vv.w);
    }
    ((float4*)(g_hsum + (size_t)w * H))[lane] = acc;
}

// ---------------- node kernel: agg = hsum@eW2 (+deg*eb2); h += gelu(h@nW1a + agg@nW1b + nb1)@nW2 + nb2 ----
__global__ __launch_bounds__(256) void k_node(const float* __restrict__ eW2, const float* __restrict__ eb2,
                                              const float* __restrict__ nW1, const float* __restrict__ nb1,
                                              const float* __restrict__ nW2, const float* __restrict__ nb2) {
    extern __shared__ float sm[];
    float* As = sm;                    // BM x LDPAD
    float* Bs = As + BM * LDPAD;       // H  x LDPAD
    float* Cs = Bs + H * LDPAD;        // BM x LDPAD
    float* Hs = Cs + BM * LDPAD;       // BM x LDPAD
    int tid = threadIdx.x, warp = tid >> 5, wr = warp >> 1, wc = warp & 1;
    int row0 = blockIdx.x * BM;

    // Stage 1: Cs(agg) = hsum @ eW2
    load_A64(As, g_hsum + (size_t)row0 * H, tid);
    load_B128(Bs, eW2, tid);
    __syncthreads();
    {
        FragC acc[4];
        #pragma unroll
        for (int j = 0; j < 4; j++) wmma::fill_fragment(acc[j], 0.f);
        gemm_tile_acc(acc, As, Bs, wr, wc);
        store_tile_s(Cs, acc, wr, wc);
    }
    __syncthreads();
    // agg += deg * eb2 (exact segment_sum of the constant bias term)
    for (int i = tid; i < BM * H; i += 256) {
        int r = i >> 7, c = i & 127;
        int n = row0 + r;
        int deg = (n < NN) ? (g_rowptr[n + 1] - g_rowptr[n]) : 0;
        Cs[r * LDPAD + c] += (float)deg * eb2[c];
    }
    // Stage 2: acc = h@nW1a + agg@nW1b
    load_A64(As, g_h + (size_t)row0 * H, tid);
    load_B128(Bs, nW1, tid);
    __syncthreads();
    FragC acc[4];
    #pragma unroll
    for (int j = 0; j < 4; j++) wmma::fill_fragment(acc[j], 0.f);
    gemm_tile_acc(acc, As, Bs, wr, wc);
    __syncthreads();
    load_B128(Bs, nW1 + H * H, tid);
    __syncthreads();
    gemm_tile_acc(acc, Cs, Bs, wr, wc);
    store_tile_s(Hs, acc, wr, wc);
    __syncthreads();
    // Hs = gelu(Hs + nb1)
    for (int i = tid; i < BM * H; i += 256) {
        int r = i >> 7, c = i & 127;
        Hs[r * LDPAD + c] = gelu_f(Hs[r * LDPAD + c] + nb1[c]);
    }
    __syncthreads();
    // Stage 3: upd = Hs @ nW2 ; h = h(As) + upd + nb2
    load_B128(Bs, nW2, tid);
    __syncthreads();
    {
        FragC a2[4];
        #pragma unroll
        for (int j = 0; j < 4; j++) wmma::fill_fragment(a2[j], 0.f);
        gemm_tile_acc(a2, Hs, Bs, wr, wc);
        store_tile_s(Cs, a2, wr, wc);
    }
    __syncthreads();
    for (int i = tid; i < BM * H; i += 256) {
        int r = i >> 7, c = i & 127;
        int n = row0 + r;
        g_h[(size_t)n * H + c] = As[r * LDPAD + c] + Cs[r * LDPAD + c] + nb2[c];
    }
}

// ---------------- decode: out = MLP2_{128->128->8}(h), SIMT fp32 (exact) ----------------
__global__ void k_decode(const float* __restrict__ W1, const float* __restrict__ b1,
                         const float* __restrict__ W2, const float* __restrict__ b2,
                         float* __restrict__ out) {
    extern __shared__ float sm[];
    float* W1s = sm;                 // H*H
    float* W2s = W1s + H * H;        // H*DOUT
    float* hid = W2s + H * DOUT;     // H
    float* hs  = hid + H;            // H
    int tid = threadIdx.x;
    for (int i = tid; i < H * H;    i += 128) W1s[i] = W1[i];
    for (int i = tid; i < H * DOUT; i += 128) W2s[i] = W2[i];
    float b1r = b1[tid];
    __syncthreads();
    int n0 = blockIdx.x * 64;
    for (int n = n0; n < n0 + 64 && n < NN; n++) {
        hs[tid] = g_h[(size_t)n * H + tid];
        __syncthreads();
        float a = b1r;
        #pragma unroll 8
        for (int k = 0; k < H; k++) a += hs[k] * W1s[k * H + tid];
        hid[tid] = gelu_f(a);
        __syncthreads();
        if (tid < DOUT) {
            float o = b2[tid];
            #pragma unroll 8
            for (int k = 0; k < H; k++) o += hid[k] * W2s[k * DOUT + tid];
            out[n * DOUT + tid] = o;
        }
        __syncthreads();
    }
}

// ---------------- launch ----------------
#define UV_SMEM   ((BM + H) * LDPAD * 4)
#define NODE_SMEM ((BM + H + BM + BM) * LDPAD * 4)
#define ENC_SMEM  ((DIN * H + H * H + H + DIN) * 4)
#define DEC_SMEM  ((H * H + H * DOUT + H + H) * 4)

extern "C" void kernel_launch(void* const* d_in, const int* in_sizes, int n_in,
                              void* d_out, int out_size) {
    const float* x     = (const float*)d_in[0];
    const int*   ei    = (const int*)d_in[1];
    const float* encW1 = (const float*)d_in[2];
    const float* encb1 = (const float*)d_in[3];
    const float* encW2 = (const float*)d_in[4];
    const float* encb2 = (const float*)d_in[5];
    const float* eW1   = (const float*)d_in[6];
    const float* eb1   = (const float*)d_in[7];
    const float* eW2   = (const float*)d_in[8];
    const float* eb2   = (const float*)d_in[9];
    const float* nW1   = (const float*)d_in[10];
    const float* nb1   = (const float*)d_in[11];
    const float* nW2   = (const float*)d_in[12];
    const float* nb2   = (const float*)d_in[13];
    const float* dW1   = (const float*)d_in[14];
    const float* db1   = (const float*)d_in[15];
    const float* dW2   = (const float*)d_in[16];
    const float* db2   = (const float*)d_in[17];
    float* out = (float*)d_out;

    cudaFuncSetAttribute(k_uv,     cudaFuncAttributeMaxDynamicSharedMemorySize, UV_SMEM);
    cudaFuncSetAttribute(k_node,   cudaFuncAttributeMaxDynamicSharedMemorySize, NODE_SMEM);
    cudaFuncSetAttribute(k_encode, cudaFuncAttributeMaxDynamicSharedMemorySize, ENC_SMEM);
    cudaFuncSetAttribute(k_decode, cudaFuncAttributeMaxDynamicSharedMemorySize, DEC_SMEM);

    const int* src = ei;
    const int* dst = ei + NE;

    // CSR build (per-launch, amortized over the 4 layers)
    k_zero_tmp<<<(NN + 255) / 256, 256>>>();
    k_count<<<(NE + 255) / 256, 256>>>(dst);
    k_scan<<<1, 1024>>>();
    k_zero_tmp<<<(NN + 255) / 256, 256>>>();
    k_fill<<<(NE + 255) / 256, 256>>>(src, dst);

    k_encode<<<NPAD / 64, 128, ENC_SMEM>>>(x, encW1, encb1, encW2, encb2);

    for (int l = 0; l < NL; l++) {
        k_uv<<<dim3(NPAD / BM, 2), 256, UV_SMEM>>>(eW1 + (size_t)l * 2 * H * H);
        k_edge<<<(NN + 7) / 8, 256>>>(eb1 + (size_t)l * H);
        k_node<<<NPAD / BM, 256, NODE_SMEM>>>(eW2 + (size_t)l * H * H, eb2 + (size_t)l * H,
                                              nW1 + (size_t)l * 2 * H * H, nb1 + (size_t)l * H,
                                              nW2 + (size_t)l * H * H, nb2 + (size_t)l * H);
    }

    k_decode<<<(NN + 63) / 64, 128, DEC_SMEM>>>(dW1, db1, dW2, db2, out);
}

// round 3
// speedup vs baseline: 1.7862x; 1.7862x over previous
#include <cuda_runtime.h>
#include <cuda_bf16.h>
#include <mma.h>

using namespace nvcuda;
typedef __nv_bfloat16 bf;

#define NN   50000
#define NE   800000
#define H    128
#define DIN  16
#define DOUT 8
#define NL   4
#define BM   64
#define LDB  136    // bf16 element stride (272 B/row; 8 rows cover all 32 banks)
#define LDC  136    // fp32 element stride
#define NPAD 50048  // 782 * 64

// ---------------- persistent device scratch ----------------
__device__ float g_h[NPAD * H];
__device__ float g_u[NPAD * H];
__device__ float g_v[NPAD * H];
__device__ float g_hsum[NPAD * H];
__device__ int   g_rowptr[NN + 1];
__device__ int   g_tmp[NN];
__device__ int   g_srcs[NE];

__device__ __forceinline__ float gelu_f(float v) {
    return 0.5f * v * (1.0f + erff(v * 0.7071067811865476f));
}

// ---------------- CSR build ----------------
__global__ void k_zero_tmp() {
    int i = blockIdx.x * blockDim.x + threadIdx.x;
    if (i < NN) g_tmp[i] = 0;
}
__global__ void k_count(const int* __restrict__ dst) {
    int e = blockIdx.x * blockDim.x + threadIdx.x;
    if (e < NE) atomicAdd(&g_tmp[dst[e]], 1);
}
__global__ void k_scan() {
    __shared__ int s[1024];
    int t = threadIdx.x;
    int carry = 0;
    for (int base = 0; base < NN; base += 1024) {
        int i = base + t;
        int v = (i < NN) ? g_tmp[i] : 0;
        s[t] = v;
        __syncthreads();
        for (int off = 1; off < 1024; off <<= 1) {
            int x = (t >= off) ? s[t - off] : 0;
            __syncthreads();
            s[t] += x;
            __syncthreads();
        }
        if (i < NN) g_rowptr[i] = carry + s[t] - v;
        int tot = s[1023];
        __syncthreads();
        carry += tot;
    }
    if (t == 0) g_rowptr[NN] = carry;
}
__global__ void k_fill(const int* __restrict__ src, const int* __restrict__ dst) {
    int e = blockIdx.x * blockDim.x + threadIdx.x;
    if (e < NE) {
        int d = dst[e];
        int pos = g_rowptr[d] + atomicAdd(&g_tmp[d], 1);
        g_srcs[pos] = src[e];
    }
}

// ---------------- bf16 hi/lo split helpers ----------------
__device__ __forceinline__ void split1(float x, bf& h, bf& l) {
    h = __float2bfloat16_rn(x);
    l = __float2bfloat16_rn(x - __bfloat162float(h));
}

// gmem fp32 [64 x 128] (row stride H) -> smem bf16 hi/lo [64 x LDB]
__device__ __forceinline__ void loadsplit_A64(bf* Ahi, bf* Alo, const float* __restrict__ src, int tid) {
    const float4* S = (const float4*)src;
    #pragma unroll 4
    for (int i = tid; i < 64 * 32; i += 256) {
        int r = i >> 5, c4 = (i & 31) << 2;
        float4 t = S[i];
        int o = r * LDB + c4;
        bf h0, l0, h1, l1, h2, l2, h3, l3;
        split1(t.x, h0, l0); split1(t.y, h1, l1);
        split1(t.z, h2, l2); split1(t.w, h3, l3);
        Ahi[o] = h0; Ahi[o+1] = h1; Ahi[o+2] = h2; Ahi[o+3] = h3;
        Alo[o] = l0; Alo[o+1] = l1; Alo[o+2] = l2; Alo[o+3] = l3;
    }
}

// gmem fp32 [128 x 128] -> smem bf16 hi/lo [128 x LDB]
__device__ __forceinline__ void loadsplit_B128(bf* Bhi, bf* Blo, const float* __restrict__ W, int tid) {
    const float4* S = (const float4*)W;
    #pragma unroll 4
    for (int i = tid; i < 128 * 32; i += 256) {
        int r = i >> 5, c4 = (i & 31) << 2;
        float4 t = S[i];
        int o = r * LDB + c4;
        bf h0, l0, h1, l1, h2, l2, h3, l3;
        split1(t.x, h0, l0); split1(t.y, h1, l1);
        split1(t.z, h2, l2); split1(t.w, h3, l3);
        Bhi[o] = h0; Bhi[o+1] = h1; Bhi[o+2] = h2; Bhi[o+3] = h3;
        Blo[o] = l0; Blo[o+1] = l1; Blo[o+2] = l2; Blo[o+3] = l3;
    }
}

// smem fp32 Cs [64 x LDC] -> smem bf16 hi/lo [64 x LDB]
__device__ __forceinline__ void split_C(const float* Cs, bf* Ahi, bf* Alo, int tid) {
    #pragma unroll 4
    for (int i = tid; i < 64 * 128; i += 256) {
        int r = i >> 7, c = i & 127;
        float x = Cs[r * LDC + c];
        bf h, l;
        split1(x, h, l);
        Ahi[r * LDB + c] = h;
        Alo[r * LDB + c] = l;
    }
}

// ---------------- wmma bf16x3 core ----------------
typedef wmma::fragment<wmma::matrix_a, 16, 16, 16, bf, wmma::row_major> FA;
typedef wmma::fragment<wmma::matrix_b, 16, 16, 16, bf, wmma::row_major> FB;
typedef wmma::fragment<wmma::accumulator, 16, 16, 16, float> FC;

__device__ __forceinline__ void gemm_bf3(FC (&acc)[4], const bf* Ahi, const bf* Alo,
                                         const bf* Bhi, const bf* Blo, int wr, int wc) {
    #pragma unroll
    for (int k = 0; k < H; k += 16) {
        FA ah, al;
        wmma::load_matrix_sync(ah, Ahi + wr * 16 * LDB + k, LDB);
        wmma::load_matrix_sync(al, Alo + wr * 16 * LDB + k, LDB);
        #pragma unroll
        for (int j = 0; j < 4; j++) {
            FB bh, bl;
            wmma::load_matrix_sync(bh, Bhi + k * LDB + wc * 64 + j * 16, LDB);
            wmma::load_matrix_sync(bl, Blo + k * LDB + wc * 64 + j * 16, LDB);
            wmma::mma_sync(acc[j], al, bh, acc[j]);
            wmma::mma_sync(acc[j], ah, bl, acc[j]);
            wmma::mma_sync(acc[j], ah, bh, acc[j]);
        }
    }
}

__device__ __forceinline__ void store_tile_s(float* Cs, FC (&acc)[4], int wr, int wc) {
    #pragma unroll
    for (int j = 0; j < 4; j++)
        wmma::store_matrix_sync(Cs + wr * 16 * LDC + wc * 64 + j * 16, acc[j], LDC,
                                wmma::mem_row_major);
}

// ---------------- encode: h = MLP2_{16->128->128}(x) ----------------
// SIMT exact for K=16 stage; bf16x3 wmma for the 128x128 stage.
__global__ __launch_bounds__(256) void k_encode(const float* __restrict__ x,
                         const float* __restrict__ W1, const float* __restrict__ b1,
                         const float* __restrict__ W2, const float* __restrict__ b2) {
    extern __shared__ char smc[];
    float* xs  = (float*)smc;                  // 64 x 16
    float* W1s = xs + 64 * DIN;                // 16 x 128
    float* Cs  = W1s + DIN * H;                // 64 x LDC
    bf* Ahi = (bf*)(Cs + 64 * LDC);
    bf* Alo = Ahi + 64 * LDB;
    bf* Bhi = Alo + 64 * LDB;
    bf* Blo = Bhi + 128 * LDB;
    int tid = threadIdx.x, warp = tid >> 5, wr = warp >> 1, wc = warp & 1;
    int row0 = blockIdx.x * BM;

    {   // load x tile (guard pad), W1
        const float4* X4 = (const float4*)x;
        for (int i = tid; i < 64 * DIN / 4; i += 256) {
            int r = i >> 2, c4 = i & 3;
            int n = row0 + r;
            float4 t = (n < NN) ? X4[n * 4 + c4] : make_float4(0.f, 0.f, 0.f, 0.f);
            *(float4*)(xs + r * DIN + c4 * 4) = t;
        }
        const float4* W4 = (const float4*)W1;
        for (int i = tid; i < DIN * H / 4; i += 256)
            *(float4*)(W1s + i * 4) = W4[i];
    }
    loadsplit_B128(Bhi, Blo, W2, tid);
    __syncthreads();
    // SIMT hidden = gelu(x@W1 + b1)
    #pragma unroll
    for (int i = tid; i < 64 * H; i += 256) {
        int r = i >> 7, c = i & 127;
        float a = __ldg(b1 + c);
        #pragma unroll
        for (int k = 0; k < DIN; k++) a += xs[r * DIN + k] * W1s[k * H + c];
        Cs[r * LDC + c] = gelu_f(a);
    }
    __syncthreads();
    split_C(Cs, Ahi, Alo, tid);
    __syncthreads();
    FC acc[4];
    #pragma unroll
    for (int j = 0; j < 4; j++) wmma::fill_fragment(acc[j], 0.f);
    gemm_bf3(acc, Ahi, Alo, Bhi, Blo, wr, wc);
    store_tile_s(Cs, acc, wr, wc);
    __syncthreads();
    for (int i = tid; i < 64 * H; i += 256) {
        int r = i >> 7, c = i & 127;
        int n = row0 + r;
        g_h[(size_t)n * H + c] = (n < NN) ? (Cs[r * LDC + c] + __ldg(b2 + c)) : 0.f;
    }
}

// ---------------- u/v: u = h@W1_top, v = h@W1_bot ----------------
__global__ __launch_bounds__(256) void k_uv(const float* __restrict__ W1) {
    extern __shared__ char smc[];
    bf* Ahi = (bf*)smc;
    bf* Alo = Ahi + 64 * LDB;
    bf* Bhi = Alo + 64 * LDB;
    bf* Blo = Bhi + 128 * LDB;
    int tid = threadIdx.x, warp = tid >> 5, wr = warp >> 1, wc = warp & 1;
    int row0 = blockIdx.x * BM;
    const float* W = W1 + (size_t)blockIdx.y * H * H;
    float* out = blockIdx.y ? g_v : g_u;
    loadsplit_A64(Ahi, Alo, g_h + (size_t)row0 * H, tid);
    loadsplit_B128(Bhi, Blo, W, tid);
    __syncthreads();
    FC acc[4];
    #pragma unroll
    for (int j = 0; j < 4; j++) wmma::fill_fragment(acc[j], 0.f);
    gemm_bf3(acc, Ahi, Alo, Bhi, Blo, wr, wc);
    #pragma unroll
    for (int j = 0; j < 4; j++)
        wmma::store_matrix_sync(out + (size_t)(row0 + wr * 16) * H + wc * 64 + j * 16,
                                acc[j], H, wmma::mem_row_major);
}

// ---------------- edge: hsum[n] = sum_{s in seg(n)} gelu(u[s]+v[n]+b1) ----------------
__global__ void k_edge(const float* __restrict__ eb1) {
    int w = (blockIdx.x * blockDim.x + threadIdx.x) >> 5;
    int lane = threadIdx.x & 31;
    if (w >= NPAD) return;
    if (w >= NN) {   // keep pad rows deterministic zeros
        ((float4*)(g_hsum + (size_t)w * H))[lane] = make_float4(0.f, 0.f, 0.f, 0.f);
        return;
    }
    float4 vv = ((const float4*)(g_v + (size_t)w * H))[lane];
    float4 bb = ((const float4*)eb1)[lane];
    vv.x += bb.x; vv.y += bb.y; vv.z += bb.z; vv.w += bb.w;
    float4 acc = make_float4(0.f, 0.f, 0.f, 0.f);
    int p1 = g_rowptr[w + 1];
    for (int p = g_rowptr[w]; p < p1; p++) {
        int s = g_srcs[p];
        float4 uu = ((const float4*)(g_u + (size_t)s * H))[lane];
        acc.x += gelu_f(uu.x + vv.x);
        acc.y += gelu_f(uu.y + vv.y);
        acc.z += gelu_f(uu.z + vv.z);
        acc.w += gelu_f(uu.w + vv.w);
    }
    ((float4*)(g_hsum + (size_t)w * H))[lane] = acc;
}

// ---------------- node: agg = hsum@eW2 + deg*eb2; h += gelu(h@nW1a + agg@nW1b + nb1)@nW2 + nb2 ----
__global__ __launch_bounds__(256) void k_node(const float* __restrict__ eW2, const float* __restrict__ eb2,
                                              const float* __restrict__ nW1, const float* __restrict__ nb1,
                                              const float* __restrict__ nW2, const float* __restrict__ nb2) {
    extern __shared__ char smc[];
    bf* Ah_hi = (bf*)smc;               // h split
    bf* Ah_lo = Ah_hi + 64 * LDB;
    bf* Aa_hi = Ah_lo + 64 * LDB;       // hsum/agg/G split
    bf* Aa_lo = Aa_hi + 64 * LDB;
    bf* Bhi   = Aa_lo + 64 * LDB;
    bf* Blo   = Bhi + 128 * LDB;
    float* Cs = (float*)(Blo + 128 * LDB);
    int tid = threadIdx.x, warp = tid >> 5, wr = warp >> 1, wc = warp & 1;
    int row0 = blockIdx.x * BM;

    loadsplit_A64(Ah_hi, Ah_lo, g_h + (size_t)row0 * H, tid);
    loadsplit_A64(Aa_hi, Aa_lo, g_hsum + (size_t)row0 * H, tid);
    loadsplit_B128(Bhi, Blo, eW2, tid);
    __syncthreads();

    // Stage 1: Cs = hsum @ eW2
    {
        FC acc[4];
        #pragma unroll
        for (int j = 0; j < 4; j++) wmma::fill_fragment(acc[j], 0.f);
        gemm_bf3(acc, Aa_hi, Aa_lo, Bhi, Blo, wr, wc);
        store_tile_s(Cs, acc, wr, wc);
    }
    __syncthreads();
    // Cs += deg * eb2 (exact segment-sum of bias)
    for (int i = tid; i < 64 * H; i += 256) {
        int r = i >> 7, c = i & 127;
        int n = row0 + r;
        int deg = (n < NN) ? (g_rowptr[n + 1] - g_rowptr[n]) : 0;
        Cs[r * LDC + c] += (float)deg * __ldg(eb2 + c);
    }
    __syncthreads();
    split_C(Cs, Aa_hi, Aa_lo, tid);           // Aa = split(agg)
    loadsplit_B128(Bhi, Blo, nW1, tid);       // B = nW1a
    __syncthreads();

    // Stage 2: acc = h@nW1a + agg@nW1b
    FC acc[4];
    #pragma unroll
    for (int j = 0; j < 4; j++) wmma::fill_fragment(acc[j], 0.f);
    gemm_bf3(acc, Ah_hi, Ah_lo, Bhi, Blo, wr, wc);
    __syncthreads();
    loadsplit_B128(Bhi, Blo, nW1 + H * H, tid);  // B = nW1b
    __syncthreads();
    gemm_bf3(acc, Aa_hi, Aa_lo, Bhi, Blo, wr, wc);
    store_tile_s(Cs, acc, wr, wc);
    __syncthreads();
    // Cs = gelu(Cs + nb1)
    for (int i = tid; i < 64 * H; i += 256) {
        int r = i >> 7, c = i & 127;
        Cs[r * LDC + c] = gelu_f(Cs[r * LDC + c] + __ldg(nb1 + c));
    }
    __syncthreads();
    split_C(Cs, Aa_hi, Aa_lo, tid);           // Aa = split(G)
    loadsplit_B128(Bhi, Blo, nW2, tid);
    __syncthreads();

    // Stage 3: Cs = G @ nW2
    {
        FC a2[4];
        #pragma unroll
        for (int j = 0; j < 4; j++) wmma::fill_fragment(a2[j], 0.f);
        gemm_bf3(a2, Aa_hi, Aa_lo, Bhi, Blo, wr, wc);
        store_tile_s(Cs, a2, wr, wc);
    }
    __syncthreads();
    // h = h (exact fp32 reload) + Cs + nb2
    for (int i = tid; i < 64 * H; i += 256) {
        int r = i >> 7, c = i & 127;
        size_t o = (size_t)(row0 + r) * H + c;
        g_h[o] = g_h[o] + Cs[r * LDC + c] + __ldg(nb2 + c);
    }
}

// ---------------- decode: out = MLP2_{128->128->8}(h) ----------------
__global__ __launch_bounds__(256) void k_decode(const float* __restrict__ W1, const float* __restrict__ b1,
                         const float* __restrict__ W2, const float* __restrict__ b2,
                         float* __restrict__ out) {
    extern __shared__ char smc[];
    float* Cs  = (float*)smc;                  // 64 x LDC
    float* W2s = Cs + 64 * LDC;                // 128 x 8
    bf* Ahi = (bf*)(W2s + H * DOUT);
    bf* Alo = Ahi + 64 * LDB;
    bf* Bhi = Alo + 64 * LDB;
    bf* Blo = Bhi + 128 * LDB;
    int tid = threadIdx.x, warp = tid >> 5, wr = warp >> 1, wc = warp & 1;
    int row0 = blockIdx.x * BM;

    loadsplit_A64(Ahi, Alo, g_h + (size_t)row0 * H, tid);
    loadsplit_B128(Bhi, Blo, W1, tid);
    {
        const float4* W4 = (const float4*)W2;
        for (int i = tid; i < H * DOUT / 4; i += 256)
            *(float4*)(W2s + i * 4) = W4[i];
    }
    __syncthreads();
    FC acc[4];
    #pragma unroll
    for (int j = 0; j < 4; j++) wmma::fill_fragment(acc[j], 0.f);
    gemm_bf3(acc, Ahi, Alo, Bhi, Blo, wr, wc);
    store_tile_s(Cs, acc, wr, wc);
    __syncthreads();
    for (int i = tid; i < 64 * H; i += 256) {
        int r = i >> 7, c = i & 127;
        Cs[r * LDC + c] = gelu_f(Cs[r * LDC + c] + __ldg(b1 + c));
    }
    __syncthreads();
    // exact SIMT 128->8 stage
    for (int i = tid; i < 64 * DOUT; i += 256) {
        int r = i >> 3, o = i & 7;
        int n = row0 + r;
        if (n >= NN) continue;
        float a = __ldg(b2 + o);
        #pragma unroll 16
        for (int k = 0; k < H; k++) a += Cs[r * LDC + k] * W2s[k * DOUT + o];
        out[n * DOUT + o] = a;
    }
}

// ---------------- launch ----------------
#define UV_SMEM   ((2*64 + 2*128) * LDB * 2)
#define NODE_SMEM ((4*64 + 2*128) * LDB * 2 + 64 * LDC * 4)
#define ENC_SMEM  ((64*DIN + DIN*H + 64*LDC) * 4 + (2*64 + 2*128) * LDB * 2)
#define DEC_SMEM  ((64*LDC + H*DOUT) * 4 + (2*64 + 2*128) * LDB * 2)

extern "C" void kernel_launch(void* const* d_in, const int* in_sizes, int n_in,
                              void* d_out, int out_size) {
    const float* x     = (const float*)d_in[0];
    const int*   ei    = (const int*)d_in[1];
    const float* encW1 = (const float*)d_in[2];
    const float* encb1 = (const float*)d_in[3];
    const float* encW2 = (const float*)d_in[4];
    const float* encb2 = (const float*)d_in[5];
    const float* eW1   = (const float*)d_in[6];
    const float* eb1   = (const float*)d_in[7];
    const float* eW2   = (const float*)d_in[8];
    const float* eb2   = (const float*)d_in[9];
    const float* nW1   = (const float*)d_in[10];
    const float* nb1   = (const float*)d_in[11];
    const float* nW2   = (const float*)d_in[12];
    const float* nb2   = (const float*)d_in[13];
    const float* dW1   = (const float*)d_in[14];
    const float* db1   = (const float*)d_in[15];
    const float* dW2   = (const float*)d_in[16];
    const float* db2   = (const float*)d_in[17];
    float* out = (float*)d_out;

    cudaFuncSetAttribute(k_uv,     cudaFuncAttributeMaxDynamicSharedMemorySize, UV_SMEM);
    cudaFuncSetAttribute(k_node,   cudaFuncAttributeMaxDynamicSharedMemorySize, NODE_SMEM);
    cudaFuncSetAttribute(k_encode, cudaFuncAttributeMaxDynamicSharedMemorySize, ENC_SMEM);
    cudaFuncSetAttribute(k_decode, cudaFuncAttributeMaxDynamicSharedMemorySize, DEC_SMEM);

    const int* src = ei;
    const int* dst = ei + NE;

    k_zero_tmp<<<(NN + 255) / 256, 256>>>();
    k_count<<<(NE + 255) / 256, 256>>>(dst);
    k_scan<<<1, 1024>>>();
    k_zero_tmp<<<(NN + 255) / 256, 256>>>();
    k_fill<<<(NE + 255) / 256, 256>>>(src, dst);

    k_encode<<<NPAD / BM, 256, ENC_SMEM>>>(x, encW1, encb1, encW2, encb2);

    for (int l = 0; l < NL; l++) {
        k_uv<<<dim3(NPAD / BM, 2), 256, UV_SMEM>>>(eW1 + (size_t)l * 2 * H * H);
        k_edge<<<NPAD / 8, 256>>>(eb1 + (size_t)l * H);
        k_node<<<NPAD / BM, 256, NODE_SMEM>>>(eW2 + (size_t)l * H * H, eb2 + (size_t)l * H,
                                              nW1 + (size_t)l * 2 * H * H, nb1 + (size_t)l * H,
                                              nW2 + (size_t)l * H * H, nb2 + (size_t)l * H);
    }

    k_decode<<<NPAD / BM, 256, DEC_SMEM>>>(dW1, db1, dW2, db2, out);
}

// round 4
// speedup vs baseline: 1.8067x; 1.0115x over previous
#include <cuda_runtime.h>
#include <cuda_bf16.h>
#include <mma.h>

using namespace nvcuda;
typedef __nv_bfloat16 bf;

#define NN   50000
#define NE   800000
#define H    128
#define DIN  16
#define DOUT 8
#define NL   4
#define BM   64
#define LDB  136
#define LDC  136
#define NPAD 50048  // 782 * 64

// weight matrix indices into the pre-split buffers (each matrix = 16384 elems)
#define W_ENCW2      0
#define W_EW1(l,h)   (1 + (l)*2 + (h))
#define W_EW2(l)     (9 + (l))
#define W_NW1(l,h)   (13 + (l)*2 + (h))
#define W_NW2(l)     (21 + (l))
#define W_DECW1      25
#define NW_TOT       26
#define W_ELEMS      (NW_TOT * H * H)   // 425984

// ---------------- persistent device scratch ----------------
__device__ float g_h[NPAD * H];
__device__ float g_u[NPAD * H];
__device__ float g_v[NPAD * H];
__device__ float g_hsum[NPAD * H];
__device__ int   g_rowptr[NN + 1];
__device__ int   g_tmp[NN];
__device__ int   g_srcs[NE];
__device__ __align__(16) bf g_whi[W_ELEMS];
__device__ __align__(16) bf g_wlo[W_ELEMS];

__device__ __forceinline__ float gelu_f(float v) {
    return 0.5f * v * (1.0f + erff(v * 0.7071067811865476f));
}

// ---------------- CSR build ----------------
__global__ void k_zero_tmp() {
    int i = blockIdx.x * blockDim.x + threadIdx.x;
    if (i < NN) g_tmp[i] = 0;
}
__global__ void k_count(const int* __restrict__ dst) {
    int e = blockIdx.x * blockDim.x + threadIdx.x;
    if (e < NE) atomicAdd(&g_tmp[dst[e]], 1);
}
__global__ void k_scan() {
    __shared__ int s[1024];
    int t = threadIdx.x;
    int carry = 0;
    for (int base = 0; base < NN; base += 1024) {
        int i = base + t;
        int v = (i < NN) ? g_tmp[i] : 0;
        s[t] = v;
        __syncthreads();
        for (int off = 1; off < 1024; off <<= 1) {
            int x = (t >= off) ? s[t - off] : 0;
            __syncthreads();
            s[t] += x;
            __syncthreads();
        }
        if (i < NN) g_rowptr[i] = carry + s[t] - v;
        int tot = s[1023];
        __syncthreads();
        carry += tot;
    }
    if (t == 0) g_rowptr[NN] = carry;
}
__global__ void k_fill(const int* __restrict__ src, const int* __restrict__ dst) {
    int e = blockIdx.x * blockDim.x + threadIdx.x;
    if (e < NE) {
        int d = dst[e];
        int pos = g_rowptr[d] + atomicAdd(&g_tmp[d], 1);
        g_srcs[pos] = src[e];
    }
}

// ---------------- weight pre-split (one shot, exact same hi/lo math) ----------------
struct WSrc { const float *encW2, *eW1, *eW2, *nW1, *nW2, *decW1; };

__global__ void k_split_w(WSrc ws) {
    int i = blockIdx.x * blockDim.x + threadIdx.x;
    if (i >= W_ELEMS) return;
    float x;
    if      (i < 1  * 16384) x = ws.encW2[i];
    else if (i < 9  * 16384) x = ws.eW1 [i - 1  * 16384];
    else if (i < 13 * 16384) x = ws.eW2 [i - 9  * 16384];
    else if (i < 21 * 16384) x = ws.nW1 [i - 13 * 16384];
    else if (i < 25 * 16384) x = ws.nW2 [i - 21 * 16384];
    else                     x = ws.decW1[i - 25 * 16384];
    bf h = __float2bfloat16_rn(x);
    g_whi[i] = h;
    g_wlo[i] = __float2bfloat16_rn(x - __bfloat162float(h));
}

// ---------------- smem staging helpers ----------------
__device__ __forceinline__ void split1(float x, bf& h, bf& l) {
    h = __float2bfloat16_rn(x);
    l = __float2bfloat16_rn(x - __bfloat162float(h));
}

// copy pre-split weight matrix widx into padded smem tiles (pure bf16 copy)
__device__ __forceinline__ void copy_B(bf* Bhi, bf* Blo, int widx, int tid) {
    const uint4* Sh = (const uint4*)(const void*)(g_whi + (size_t)widx * 16384);
    const uint4* Sl = (const uint4*)(const void*)(g_wlo + (size_t)widx * 16384);
    #pragma unroll 4
    for (int i = tid; i < 2048; i += 256) {
        int r = i >> 4, c8 = (i & 15) << 3;
        *(uint4*)(Bhi + r * LDB + c8) = Sh[i];
        *(uint4*)(Blo + r * LDB + c8) = Sl[i];
    }
}

// gmem fp32 [64 x 128] (stride H) -> smem bf16 hi/lo [64 x LDB]
__device__ __forceinline__ void loadsplit_A64(bf* Ahi, bf* Alo, const float* __restrict__ src, int tid) {
    const float4* S = (const float4*)src;
    #pragma unroll 4
    for (int i = tid; i < 64 * 32; i += 256) {
        int r = i >> 5, c4 = (i & 31) << 2;
        float4 t = S[i];
        int o = r * LDB + c4;
        bf h0, l0, h1, l1, h2, l2, h3, l3;
        split1(t.x, h0, l0); split1(t.y, h1, l1);
        split1(t.z, h2, l2); split1(t.w, h3, l3);
        Ahi[o] = h0; Ahi[o+1] = h1; Ahi[o+2] = h2; Ahi[o+3] = h3;
        Alo[o] = l0; Alo[o+1] = l1; Alo[o+2] = l2; Alo[o+3] = l3;
    }
}

// smem fp32 Cs [64 x LDC] -> smem bf16 hi/lo [64 x LDB]
__device__ __forceinline__ void split_C(const float* Cs, bf* Ahi, bf* Alo, int tid) {
    #pragma unroll 4
    for (int i = tid; i < 64 * 128; i += 256) {
        int r = i >> 7, c = i & 127;
        bf h, l;
        split1(Cs[r * LDC + c], h, l);
        Ahi[r * LDB + c] = h;
        Alo[r * LDB + c] = l;
    }
}

// ---------------- wmma bf16x3 core ----------------
typedef wmma::fragment<wmma::matrix_a, 16, 16, 16, bf, wmma::row_major> FA;
typedef wmma::fragment<wmma::matrix_b, 16, 16, 16, bf, wmma::row_major> FB;
typedef wmma::fragment<wmma::accumulator, 16, 16, 16, float> FC;

__device__ __forceinline__ void gemm_bf3(FC (&acc)[4], const bf* Ahi, const bf* Alo,
                                         const bf* Bhi, const bf* Blo, int wr, int wc) {
    #pragma unroll
    for (int k = 0; k < H; k += 16) {
        FA ah, al;
        wmma::load_matrix_sync(ah, Ahi + wr * 16 * LDB + k, LDB);
        wmma::load_matrix_sync(al, Alo + wr * 16 * LDB + k, LDB);
        #pragma unroll
        for (int j = 0; j < 4; j++) {
            FB bh, bl;
            wmma::load_matrix_sync(bh, Bhi + k * LDB + wc * 64 + j * 16, LDB);
            wmma::load_matrix_sync(bl, Blo + k * LDB + wc * 64 + j * 16, LDB);
            wmma::mma_sync(acc[j], al, bh, acc[j]);
            wmma::mma_sync(acc[j], ah, bl, acc[j]);
            wmma::mma_sync(acc[j], ah, bh, acc[j]);
        }
    }
}

__device__ __forceinline__ void store_tile_s(float* Cs, FC (&acc)[4], int wr, int wc) {
    #pragma unroll
    for (int j = 0; j < 4; j++)
        wmma::store_matrix_sync(Cs + wr * 16 * LDC + wc * 64 + j * 16, acc[j], LDC,
                                wmma::mem_row_major);
}

__device__ __forceinline__ void gemm_to_gmem(float* out, int row0, const bf* Ahi, const bf* Alo,
                                             const bf* Bhi, const bf* Blo, int wr, int wc) {
    FC acc[4];
    #pragma unroll
    for (int j = 0; j < 4; j++) wmma::fill_fragment(acc[j], 0.f);
    gemm_bf3(acc, Ahi, Alo, Bhi, Blo, wr, wc);
    #pragma unroll
    for (int j = 0; j < 4; j++)
        wmma::store_matrix_sync(out + (size_t)(row0 + wr * 16) * H + wc * 64 + j * 16,
                                acc[j], H, wmma::mem_row_major);
}

// ---------------- encode (+ u/v for layer 0) ----------------
__global__ __launch_bounds__(256) void k_encode(const float* __restrict__ x,
                         const float* __restrict__ W1, const float* __restrict__ b1,
                         const float* __restrict__ b2) {
    extern __shared__ char smc[];
    float* xs  = (float*)smc;                  // 64 x 16
    float* W1s = xs + 64 * DIN;                // 16 x 128
    float* Cs  = W1s + DIN * H;                // 64 x LDC
    bf* Ahi = (bf*)(Cs + 64 * LDC);
    bf* Alo = Ahi + 64 * LDB;
    bf* Bhi = Alo + 64 * LDB;
    bf* Blo = Bhi + 128 * LDB;
    int tid = threadIdx.x, warp = tid >> 5, wr = warp >> 1, wc = warp & 1;
    int row0 = blockIdx.x * BM;

    {   // load x tile (pad-guarded) + W1
        const float4* X4 = (const float4*)x;
        for (int i = tid; i < 64 * DIN / 4; i += 256) {
            int r = i >> 2, c4 = i & 3;
            int n = row0 + r;
            float4 t = (n < NN) ? X4[n * 4 + c4] : make_float4(0.f, 0.f, 0.f, 0.f);
            *(float4*)(xs + r * DIN + c4 * 4) = t;
        }
        const float4* W4 = (const float4*)W1;
        for (int i = tid; i < DIN * H / 4; i += 256)
            *(float4*)(W1s + i * 4) = W4[i];
    }
    copy_B(Bhi, Blo, W_ENCW2, tid);
    __syncthreads();
    // SIMT hidden = gelu(x@W1 + b1)  (K=16, exact fp32)
    for (int i = tid; i < 64 * H; i += 256) {
        int r = i >> 7, c = i & 127;
        float a = __ldg(b1 + c);
        #pragma unroll
        for (int k = 0; k < DIN; k++) a += xs[r * DIN + k] * W1s[k * H + c];
        Cs[r * LDC + c] = gelu_f(a);
    }
    __syncthreads();
    split_C(Cs, Ahi, Alo, tid);
    __syncthreads();
    FC acc[4];
    #pragma unroll
    for (int j = 0; j < 4; j++) wmma::fill_fragment(acc[j], 0.f);
    gemm_bf3(acc, Ahi, Alo, Bhi, Blo, wr, wc);
    store_tile_s(Cs, acc, wr, wc);
    __syncthreads();
    // h = Cs + b2; write gmem (pad rows -> 0), keep value in Cs for the u/v split
    for (int i = tid; i < 64 * H; i += 256) {
        int r = i >> 7, c = i & 127;
        int n = row0 + r;
        float hv = Cs[r * LDC + c] + __ldg(b2 + c);
        g_h[(size_t)n * H + c] = (n < NN) ? hv : 0.f;
        Cs[r * LDC + c] = (n < NN) ? hv : 0.f;
    }
    __syncthreads();
    // fused u/v for layer 0
    split_C(Cs, Ahi, Alo, tid);
    copy_B(Bhi, Blo, W_EW1(0, 0), tid);
    __syncthreads();
    gemm_to_gmem(g_u, row0, Ahi, Alo, Bhi, Blo, wr, wc);
    __syncthreads();
    copy_B(Bhi, Blo, W_EW1(0, 1), tid);
    __syncthreads();
    gemm_to_gmem(g_v, row0, Ahi, Alo, Bhi, Blo, wr, wc);
}

// ---------------- edge: hsum[n] = sum_{s in seg(n)} gelu(u[s]+v[n]+b1) ----------------
__global__ void k_edge(const float* __restrict__ eb1) {
    int w = (blockIdx.x * blockDim.x + threadIdx.x) >> 5;
    int lane = threadIdx.x & 31;
    if (w >= NPAD) return;
    if (w >= NN) {
        ((float4*)(g_hsum + (size_t)w * H))[lane] = make_float4(0.f, 0.f, 0.f, 0.f);
        return;
    }
    float4 vv = ((const float4*)(g_v + (size_t)w * H))[lane];
    float4 bb = ((const float4*)eb1)[lane];
    vv.x += bb.x; vv.y += bb.y; vv.z += bb.z; vv.w += bb.w;
    float4 acc = make_float4(0.f, 0.f, 0.f, 0.f);
    int p  = g_rowptr[w];
    int p1 = g_rowptr[w + 1];
    for (; p + 2 <= p1; p += 2) {                 // 2x unroll for MLP
        int s0 = g_srcs[p], s1 = g_srcs[p + 1];
        float4 u0 = ((const float4*)(g_u + (size_t)s0 * H))[lane];
        float4 u1 = ((const float4*)(g_u + (size_t)s1 * H))[lane];
        acc.x += gelu_f(u0.x + vv.x) + gelu_f(u1.x + vv.x);
        acc.y += gelu_f(u0.y + vv.y) + gelu_f(u1.y + vv.y);
        acc.z += gelu_f(u0.z + vv.z) + gelu_f(u1.z + vv.z);
        acc.w += gelu_f(u0.w + vv.w) + gelu_f(u1.w + vv.w);
    }
    if (p < p1) {
        int s0 = g_srcs[p];
        float4 u0 = ((const float4*)(g_u + (size_t)s0 * H))[lane];
        acc.x += gelu_f(u0.x + vv.x);
        acc.y += gelu_f(u0.y + vv.y);
        acc.z += gelu_f(u0.z + vv.z);
        acc.w += gelu_f(u0.w + vv.w);
    }
    ((float4*)(g_hsum + (size_t)w * H))[lane] = acc;
}

// ---------------- node (+ fused u/v for next layer) ----------------
__global__ __launch_bounds__(256) void k_node(const float* __restrict__ eb2,
                                              const float* __restrict__ nb1,
                                              const float* __restrict__ nb2,
                                              int w_eW2, int w_nW1a, int w_nW2,
                                              int w_eW1a_next) {
    extern __shared__ char smc[];
    bf* Ah_hi = (bf*)smc;               // h split
    bf* Ah_lo = Ah_hi + 64 * LDB;
    bf* Aa_hi = Ah_lo + 64 * LDB;       // hsum/agg/G/hnew split
    bf* Aa_lo = Aa_hi + 64 * LDB;
    bf* Bhi   = Aa_lo + 64 * LDB;
    bf* Blo   = Bhi + 128 * LDB;
    float* Cs = (float*)(Blo + 128 * LDB);
    int tid = threadIdx.x, warp = tid >> 5, wr = warp >> 1, wc = warp & 1;
    int row0 = blockIdx.x * BM;

    loadsplit_A64(Ah_hi, Ah_lo, g_h + (size_t)row0 * H, tid);
    loadsplit_A64(Aa_hi, Aa_lo, g_hsum + (size_t)row0 * H, tid);
    copy_B(Bhi, Blo, w_eW2, tid);
    __syncthreads();

    // Stage 1: Cs = hsum @ eW2
    {
        FC acc[4];
        #pragma unroll
        for (int j = 0; j < 4; j++) wmma::fill_fragment(acc[j], 0.f);
        gemm_bf3(acc, Aa_hi, Aa_lo, Bhi, Blo, wr, wc);
        store_tile_s(Cs, acc, wr, wc);
    }
    __syncthreads();
    // Cs += deg * eb2
    for (int i = tid; i < 64 * H; i += 256) {
        int r = i >> 7, c = i & 127;
        int n = row0 + r;
        int deg = (n < NN) ? (g_rowptr[n + 1] - g_rowptr[n]) : 0;
        Cs[r * LDC + c] += (float)deg * __ldg(eb2 + c);
    }
    __syncthreads();
    split_C(Cs, Aa_hi, Aa_lo, tid);       // Aa = split(agg)
    copy_B(Bhi, Blo, w_nW1a, tid);
    __syncthreads();

    // Stage 2: acc = h@nW1a + agg@nW1b
    FC acc[4];
    #pragma unroll
    for (int j = 0; j < 4; j++) wmma::fill_fragment(acc[j], 0.f);
    gemm_bf3(acc, Ah_hi, Ah_lo, Bhi, Blo, wr, wc);
    __syncthreads();
    copy_B(Bhi, Blo, w_nW1a + 1, tid);
    __syncthreads();
    gemm_bf3(acc, Aa_hi, Aa_lo, Bhi, Blo, wr, wc);
    store_tile_s(Cs, acc, wr, wc);
    __syncthreads();
    // Cs = gelu(Cs + nb1)
    for (int i = tid; i < 64 * H; i += 256) {
        int r = i >> 7, c = i & 127;
        Cs[r * LDC + c] = gelu_f(Cs[r * LDC + c] + __ldg(nb1 + c));
    }
    __syncthreads();
    split_C(Cs, Aa_hi, Aa_lo, tid);       // Aa = split(G)
    copy_B(Bhi, Blo, w_nW2, tid);
    __syncthreads();

    // Stage 3: Cs = G @ nW2
    {
        FC a2[4];
        #pragma unroll
        for (int j = 0; j < 4; j++) wmma::fill_fragment(a2[j], 0.f);
        gemm_bf3(a2, Aa_hi, Aa_lo, Bhi, Blo, wr, wc);
        store_tile_s(Cs, a2, wr, wc);
    }
    __syncthreads();
    // hnew = h_old (exact fp32) + Cs + nb2 ; write gmem + keep in Cs
    for (int i = tid; i < 64 * H; i += 256) {
        int r = i >> 7, c = i & 127;
        size_t o = (size_t)(row0 + r) * H + c;
        float hn = g_h[o] + Cs[r * LDC + c] + __ldg(nb2 + c);
        g_h[o] = hn;
        Cs[r * LDC + c] = hn;
    }
    __syncthreads();

    // fused u/v for next layer
    if (w_eW1a_next >= 0) {
        split_C(Cs, Aa_hi, Aa_lo, tid);
        copy_B(Bhi, Blo, w_eW1a_next, tid);
        __syncthreads();
        gemm_to_gmem(g_u, row0, Aa_hi, Aa_lo, Bhi, Blo, wr, wc);
        __syncthreads();
        copy_B(Bhi, Blo, w_eW1a_next + 1, tid);
        __syncthreads();
        gemm_to_gmem(g_v, row0, Aa_hi, Aa_lo, Bhi, Blo, wr, wc);
    }
}

// ---------------- decode ----------------
__global__ __launch_bounds__(256) void k_decode(const float* __restrict__ b1,
                         const float* __restrict__ W2, const float* __restrict__ b2,
                         float* __restrict__ out) {
    extern __shared__ char smc[];
    float* Cs  = (float*)smc;                  // 64 x LDC
    float* W2s = Cs + 64 * LDC;                // 128 x 8
    bf* Ahi = (bf*)(W2s + H * DOUT);
    bf* Alo = Ahi + 64 * LDB;
    bf* Bhi = Alo + 64 * LDB;
    bf* Blo = Bhi + 128 * LDB;
    int tid = threadIdx.x, warp = tid >> 5, wr = warp >> 1, wc = warp & 1;
    int row0 = blockIdx.x * BM;

    loadsplit_A64(Ahi, Alo, g_h + (size_t)row0 * H, tid);
    copy_B(Bhi, Blo, W_DECW1, tid);
    {
        const float4* W4 = (const float4*)W2;
        for (int i = tid; i < H * DOUT / 4; i += 256)
            *(float4*)(W2s + i * 4) = W4[i];
    }
    __syncthreads();
    FC acc[4];
    #pragma unroll
    for (int j = 0; j < 4; j++) wmma::fill_fragment(acc[j], 0.f);
    gemm_bf3(acc, Ahi, Alo, Bhi, Blo, wr, wc);
    store_tile_s(Cs, acc, wr, wc);
    __syncthreads();
    for (int i = tid; i < 64 * H; i += 256) {
        int r = i >> 7, c = i & 127;
        Cs[r * LDC + c] = gelu_f(Cs[r * LDC + c] + __ldg(b1 + c));
    }
    __syncthreads();
    // exact SIMT 128->8 stage
    for (int i = tid; i < 64 * DOUT; i += 256) {
        int r = i >> 3, o = i & 7;
        int n = row0 + r;
        if (n >= NN) continue;
        float a = __ldg(b2 + o);
        #pragma unroll 16
        for (int k = 0; k < H; k++) a += Cs[r * LDC + k] * W2s[k * DOUT + o];
        out[n * DOUT + o] = a;
    }
}

// ---------------- launch ----------------
#define NODE_SMEM ((4*64 + 2*128) * LDB * 2 + 64 * LDC * 4)
#define ENC_SMEM  ((64*DIN + DIN*H + 64*LDC) * 4 + (2*64 + 2*128) * LDB * 2)
#define DEC_SMEM  ((64*LDC + H*DOUT) * 4 + (2*64 + 2*128) * LDB * 2)

extern "C" void kernel_launch(void* const* d_in, const int* in_sizes, int n_in,
                              void* d_out, int out_size) {
    const float* x     = (const float*)d_in[0];
    const int*   ei    = (const int*)d_in[1];
    const float* encW1 = (const float*)d_in[2];
    const float* encb1 = (const float*)d_in[3];
    const float* encW2 = (const float*)d_in[4];
    const float* encb2 = (const float*)d_in[5];
    const float* eW1   = (const float*)d_in[6];
    const float* eb1   = (const float*)d_in[7];
    const float* eW2   = (const float*)d_in[8];
    const float* eb2   = (const float*)d_in[9];
    const float* nW1   = (const float*)d_in[10];
    const float* nb1   = (const float*)d_in[11];
    const float* nW2   = (const float*)d_in[12];
    const float* nb2   = (const float*)d_in[13];
    const float* dW1   = (const float*)d_in[14];
    const float* db1   = (const float*)d_in[15];
    const float* dW2   = (const float*)d_in[16];
    const float* db2   = (const float*)d_in[17];
    float* out = (float*)d_out;

    cudaFuncSetAttribute(k_node,   cudaFuncAttributeMaxDynamicSharedMemorySize, NODE_SMEM);
    cudaFuncSetAttribute(k_encode, cudaFuncAttributeMaxDynamicSharedMemorySize, ENC_SMEM);
    cudaFuncSetAttribute(k_decode, cudaFuncAttributeMaxDynamicSharedMemorySize, DEC_SMEM);

    const int* src = ei;
    const int* dst = ei + NE;

    // CSR build
    k_zero_tmp<<<(NN + 255) / 256, 256>>>();
    k_count<<<(NE + 255) / 256, 256>>>(dst);
    k_scan<<<1, 1024>>>();
    k_zero_tmp<<<(NN + 255) / 256, 256>>>();
    k_fill<<<(NE + 255) / 256, 256>>>(src, dst);

    // one-shot weight pre-split
    WSrc ws{encW2, eW1, eW2, nW1, nW2, dW1};
    k_split_w<<<(W_ELEMS + 255) / 256, 256>>>(ws);

    k_encode<<<NPAD / BM, 256, ENC_SMEM>>>(x, encW1, encb1, encb2);

    for (int l = 0; l < NL; l++) {
        k_edge<<<NPAD / 8, 256>>>(eb1 + (size_t)l * H);
        k_node<<<NPAD / BM, 256, NODE_SMEM>>>(
            eb2 + (size_t)l * H, nb1 + (size_t)l * H, nb2 + (size_t)l * H,
            W_EW2(l), W_NW1(l, 0), W_NW2(l),
            (l + 1 < NL) ? W_EW1(l + 1, 0) : -1);
    }

    k_decode<<<NPAD / BM, 256, DEC_SMEM>>>(db1, dW2, db2, out);
}

// round 6
// speedup vs baseline: 2.4049x; 1.3310x over previous
#include <cuda_runtime.h>
#include <cuda_bf16.h>
#include <mma.h>
#include <cstdint>

using namespace nvcuda;
typedef __nv_bfloat16 bf;

#define NN   50000
#define NE   800000
#define H    128
#define DIN  16
#define DOUT 8
#define NL   4
#define LDB  136
#define LDC  136
#define NPAD 50048   // 391*128 == 782*64

// weight slots (each 16384 elems, row-major [in][out])
#define W_ENCW2     0
#define W_EW1(l,h)  (1 + (l)*2 + (h))
#define W_NW1A(l)   (9 + (l))
#define W_NW2(l)    (13 + (l))
#define W_DECW1     17
#define W_COMB(l)   (18 + (l))
#define NW_TOT      22
#define NW_SPLIT    18                       // filled by k_split_w; COMB filled by k_comb
#define W_ELEMS     (NW_TOT * H * H)

// ---------------- persistent device scratch ----------------
__device__ float g_h[NPAD * H];
__device__ float g_u[NPAD * H];
__device__ float g_v[NPAD * H];
__device__ float g_hsum[NPAD * H];
__device__ int   g_rowptr[NN + 1];
__device__ int   g_tmp[NN];
__device__ int   g_srcs[NE];
__device__ __align__(16) bf    g_whi[W_ELEMS];
__device__ __align__(16) bf    g_wlo[W_ELEMS];
__device__ __align__(16) float g_bcomb[NL * H];

__device__ __forceinline__ float gelu_f(float v) {
    return 0.5f * v * (1.0f + erff(v * 0.7071067811865476f));
}
__device__ __forceinline__ void split1(float x, bf& h, bf& l) {
    h = __float2bfloat16_rn(x);
    l = __float2bfloat16_rn(x - __bfloat162float(h));
}

// ---------------- CSR build ----------------
__global__ void k_count(const int* __restrict__ dst) {
    int e = blockIdx.x * blockDim.x + threadIdx.x;
    if (e < NE) atomicAdd(&g_tmp[dst[e]], 1);
}
__global__ void k_scan() {
    __shared__ int s[1024];
    int t = threadIdx.x;
    int carry = 0;
    for (int base = 0; base < NN; base += 1024) {
        int i = base + t;
        int v = (i < NN) ? g_tmp[i] : 0;
        s[t] = v;
        __syncthreads();
        for (int off = 1; off < 1024; off <<= 1) {
            int x = (t >= off) ? s[t - off] : 0;
            __syncthreads();
            s[t] += x;
            __syncthreads();
        }
        if (i < NN) g_rowptr[i] = carry + s[t] - v;
        int tot = s[1023];
        __syncthreads();
        carry += tot;
    }
    if (t == 0) g_rowptr[NN] = carry;
}
__global__ void k_fill(const int* __restrict__ src, const int* __restrict__ dst) {
    int e = blockIdx.x * blockDim.x + threadIdx.x;
    if (e < NE) {
        int d = dst[e];
        int pos = g_rowptr[d] + atomicAdd(&g_tmp[d], 1);
        g_srcs[pos] = src[e];
    }
}

// ---------------- weight pre-split (18 matrices, no transpose) ----------------
struct WSrc { const float *encW2, *eW1, *nW1, *nW2, *decW1; };

__global__ void k_split_w(WSrc ws) {
    int i = blockIdx.x * blockDim.x + threadIdx.x;
    if (i >= NW_SPLIT * 16384) return;
    int m = i >> 14, w = i & 16383;
    float x;
    if      (m == 0)  x = ws.encW2[w];
    else if (m <= 8)  { int q = m - 1; x = ws.eW1[(q >> 1) * 32768 + (q & 1) * 16384 + w]; }
    else if (m <= 12) x = ws.nW1[(m - 9) * 32768 + w];            // nW1a (top half)
    else if (m <= 16) x = ws.nW2[(m - 13) * 16384 + w];
    else              x = ws.decW1[w];
    bf hh = __float2bfloat16_rn(x);
    g_whi[i] = hh;
    g_wlo[i] = __float2bfloat16_rn(x - __bfloat162float(hh));
}

// ---------------- Wcomb = eW2 @ nW1b ; bcomb = eb2 @ nW1b (fp32, per layer) ----------------
__global__ __launch_bounds__(256) void k_comb(const float* __restrict__ eW2,
                                              const float* __restrict__ nW1,
                                              const float* __restrict__ eb2) {
    extern __shared__ float sm[];
    float* As = sm;            // eW2[l]  128x128
    float* Bs = sm + 16384;    // nW1b[l] 128x128
    int l = blockIdx.x, tid = threadIdx.x;
    const float* A = eW2 + (size_t)l * 16384;
    const float* B = nW1 + (size_t)l * 32768 + 16384;
    for (int i = tid; i < 16384; i += 256) { As[i] = A[i]; Bs[i] = B[i]; }
    __syncthreads();
    for (int i = tid; i < 16384; i += 256) {
        int k = i >> 7, n = i & 127;
        float s = 0.f;
        #pragma unroll 8
        for (int m = 0; m < 128; m++) s += As[k * 128 + m] * Bs[m * 128 + n];
        bf hh = __float2bfloat16_rn(s);
        size_t o = (size_t)(W_COMB(l)) * 16384 + i;
        g_whi[o] = hh;
        g_wlo[o] = __float2bfloat16_rn(s - __bfloat162float(hh));
    }
    if (tid < 128) {
        float s = 0.f;
        #pragma unroll 8
        for (int m = 0; m < 128; m++) s += __ldg(eb2 + l * 128 + m) * Bs[m * 128 + tid];
        g_bcomb[l * 128 + tid] = s;
    }
}

// ---------------- smem staging helpers ----------------
__device__ __forceinline__ void copy_Bw(bf* Bhi, bf* Blo, int widx, int tid) {
    const uint4* Sh = (const uint4*)(const void*)(g_whi + (size_t)widx * 16384);
    const uint4* Sl = (const uint4*)(const void*)(g_wlo + (size_t)widx * 16384);
    #pragma unroll 4
    for (int i = tid; i < 2048; i += 256) {
        int r = i >> 4, c8 = (i & 15) << 3;
        *(uint4*)(Bhi + r * LDB + c8) = Sh[i];
        *(uint4*)(Blo + r * LDB + c8) = Sl[i];
    }
}
__device__ __forceinline__ void split_smem4(bf* Ahi, bf* Alo, int idx, float4 v) {
    bf h0, l0, h1, l1, h2, l2, h3, l3;
    split1(v.x, h0, l0); split1(v.y, h1, l1); split1(v.z, h2, l2); split1(v.w, h3, l3);
    uint2 ph, pl;
    ph.x = (uint32_t)__bfloat16_as_ushort(h0) | ((uint32_t)__bfloat16_as_ushort(h1) << 16);
    ph.y = (uint32_t)__bfloat16_as_ushort(h2) | ((uint32_t)__bfloat16_as_ushort(h3) << 16);
    pl.x = (uint32_t)__bfloat16_as_ushort(l0) | ((uint32_t)__bfloat16_as_ushort(l1) << 16);
    pl.y = (uint32_t)__bfloat16_as_ushort(l2) | ((uint32_t)__bfloat16_as_ushort(l3) << 16);
    *(uint2*)(Ahi + idx) = ph;
    *(uint2*)(Alo + idx) = pl;
}
// gmem fp32 [rows x 128] -> smem split [rows x LDB]
template <int ROWS>
__device__ __forceinline__ void loadsplit_A(bf* Ahi, bf* Alo, const float* __restrict__ src, int tid) {
    const float4* S = (const float4*)src;
    #pragma unroll 4
    for (int i = tid; i < ROWS * 32; i += 256) {
        int r = i >> 5, c4 = (i & 31) << 2;
        float4 t = S[i];
        split_smem4(Ahi, Alo, r * LDB + c4, t);
    }
}

// ---------------- wmma bf16x3 cores ----------------
typedef wmma::fragment<wmma::matrix_a, 16, 16, 16, bf, wmma::row_major> FA;
typedef wmma::fragment<wmma::matrix_b, 16, 16, 16, bf, wmma::row_major> FB;
typedef wmma::fragment<wmma::accumulator, 16, 16, 16, float> FC;

// warp tile 16x64 (encode path, BM=64)
__device__ __forceinline__ void gemm_bf3(FC (&acc)[4], const bf* Ahi, const bf* Alo,
                                         const bf* Bhi, const bf* Blo, int wr, int wc) {
    #pragma unroll
    for (int k = 0; k < H; k += 16) {
        FA ah, al;
        wmma::load_matrix_sync(ah, Ahi + wr * 16 * LDB + k, LDB);
        wmma::load_matrix_sync(al, Alo + wr * 16 * LDB + k, LDB);
        #pragma unroll
        for (int j = 0; j < 4; j++) {
            FB bh, bl;
            wmma::load_matrix_sync(bh, Bhi + k * LDB + wc * 64 + j * 16, LDB);
            wmma::load_matrix_sync(bl, Blo + k * LDB + wc * 64 + j * 16, LDB);
            wmma::mma_sync(acc[j], al, bh, acc[j]);
            wmma::mma_sync(acc[j], ah, bl, acc[j]);
            wmma::mma_sync(acc[j], ah, bh, acc[j]);
        }
    }
}
// warp tile 32x64 (P2 path, BM=128)
__device__ __forceinline__ void gemm128(FC (&acc)[2][4], const bf* Ahi, const bf* Alo,
                                        const bf* Bhi, const bf* Blo, int wr, int wc) {
    #pragma unroll
    for (int k = 0; k < H; k += 16) {
        FA ah[2], al[2];
        #pragma unroll
        for (int rr = 0; rr < 2; rr++) {
            wmma::load_matrix_sync(ah[rr], Ahi + (wr * 32 + rr * 16) * LDB + k, LDB);
            wmma::load_matrix_sync(al[rr], Alo + (wr * 32 + rr * 16) * LDB + k, LDB);
        }
        #pragma unroll
        for (int j = 0; j < 4; j++) {
            FB bh, bl;
            wmma::load_matrix_sync(bh, Bhi + k * LDB + wc * 64 + j * 16, LDB);
            wmma::load_matrix_sync(bl, Blo + k * LDB + wc * 64 + j * 16, LDB);
            #pragma unroll
            for (int rr = 0; rr < 2; rr++) {
                wmma::mma_sync(acc[rr][j], al[rr], bh, acc[rr][j]);
                wmma::mma_sync(acc[rr][j], ah[rr], bl, acc[rr][j]);
                wmma::mma_sync(acc[rr][j], ah[rr], bh, acc[rr][j]);
            }
        }
    }
}
__device__ __forceinline__ void fill0(FC (&acc)[2][4]) {
    #pragma unroll
    for (int rr = 0; rr < 2; rr++)
        #pragma unroll
        for (int j = 0; j < 4; j++) wmma::fill_fragment(acc[rr][j], 0.f);
}
__device__ __forceinline__ void store128s(float* Cs, FC (&acc)[2][4], int wr, int wc) {
    #pragma unroll
    for (int rr = 0; rr < 2; rr++)
        #pragma unroll
        for (int j = 0; j < 4; j++)
            wmma::store_matrix_sync(Cs + (wr * 32 + rr * 16) * LDC + wc * 64 + j * 16,
                                    acc[rr][j], LDC, wmma::mem_row_major);
}
__device__ __forceinline__ void store128g(float* out, int row0, FC (&acc)[2][4], int wr, int wc) {
    #pragma unroll
    for (int rr = 0; rr < 2; rr++)
        #pragma unroll
        for (int j = 0; j < 4; j++)
            wmma::store_matrix_sync(out + (size_t)(row0 + wr * 32 + rr * 16) * H + wc * 64 + j * 16,
                                    acc[rr][j], H, wmma::mem_row_major);
}

// ---------------- encode: h = MLP2_{16->128->128}(x); fused u/v for layer 0 ----------------
__global__ __launch_bounds__(256) void k_encode(const float* __restrict__ x,
                         const float* __restrict__ W1, const float* __restrict__ b1,
                         const float* __restrict__ b2) {
    extern __shared__ char smc[];
    float* xs  = (float*)smc;                  // 64 x 16
    float* W1s = xs + 64 * DIN;                // 16 x 128
    float* Cs  = W1s + DIN * H;                // 64 x LDC
    bf* Ahi = (bf*)(Cs + 64 * LDC);
    bf* Alo = Ahi + 64 * LDB;
    bf* Bhi = Alo + 64 * LDB;
    bf* Blo = Bhi + 128 * LDB;
    int tid = threadIdx.x, warp = tid >> 5, wr = warp >> 1, wc = warp & 1;
    int row0 = blockIdx.x * 64;

    {
        const float4* X4 = (const float4*)x;
        for (int i = tid; i < 64 * DIN / 4; i += 256) {
            int r = i >> 2, c4 = i & 3;
            int n = row0 + r;
            float4 t = (n < NN) ? X4[n * 4 + c4] : make_float4(0.f, 0.f, 0.f, 0.f);
            *(float4*)(xs + r * DIN + c4 * 4) = t;
        }
        const float4* W4 = (const float4*)W1;
        for (int i = tid; i < DIN * H / 4; i += 256)
            *(float4*)(W1s + i * 4) = W4[i];
    }
    copy_Bw(Bhi, Blo, W_ENCW2, tid);
    __syncthreads();
    // SIMT hidden = gelu(x@W1 + b1), exact fp32 (K=16)
    for (int i = tid; i < 64 * H; i += 256) {
        int r = i >> 7, c = i & 127;
        float a = __ldg(b1 + c);
        #pragma unroll
        for (int k = 0; k < DIN; k++) a += xs[r * DIN + k] * W1s[k * H + c];
        Cs[r * LDC + c] = gelu_f(a);
    }
    __syncthreads();
    // split hidden -> A
    for (int i = tid; i < 64 * 32; i += 256) {
        int r = i >> 5, c4 = (i & 31) << 2;
        float4 v = *(float4*)(Cs + r * LDC + c4);
        split_smem4(Ahi, Alo, r * LDB + c4, v);
    }
    __syncthreads();
    FC acc[4];
    #pragma unroll
    for (int j = 0; j < 4; j++) wmma::fill_fragment(acc[j], 0.f);
    gemm_bf3(acc, Ahi, Alo, Bhi, Blo, wr, wc);
    #pragma unroll
    for (int j = 0; j < 4; j++)
        wmma::store_matrix_sync(Cs + wr * 16 * LDC + wc * 64 + j * 16, acc[j], LDC,
                                wmma::mem_row_major);
    __syncthreads();
    // h = Cs + b2 (pad rows zero); write g_h; split -> A for uv0
    for (int i = tid; i < 64 * 32; i += 256) {
        int r = i >> 5, c4 = (i & 31) << 2;
        int n = row0 + r;
        float4 v = *(float4*)(Cs + r * LDC + c4);
        float4 b = *(const float4*)(b2 + c4);
        v.x += b.x; v.y += b.y; v.z += b.z; v.w += b.w;
        if (n >= NN) v = make_float4(0.f, 0.f, 0.f, 0.f);
        *(float4*)(g_h + (size_t)n * H + c4) = v;
        split_smem4(Ahi, Alo, r * LDB + c4, v);
    }
    copy_Bw(Bhi, Blo, W_EW1(0, 0), tid);
    __syncthreads();
    {
        FC a2[4];
        #pragma unroll
        for (int j = 0; j < 4; j++) wmma::fill_fragment(a2[j], 0.f);
        gemm_bf3(a2, Ahi, Alo, Bhi, Blo, wr, wc);
        #pragma unroll
        for (int j = 0; j < 4; j++)
            wmma::store_matrix_sync(g_u + (size_t)(row0 + wr * 16) * H + wc * 64 + j * 16,
                                    a2[j], H, wmma::mem_row_major);
    }
    __syncthreads();
    copy_Bw(Bhi, Blo, W_EW1(0, 1), tid);
    __syncthreads();
    {
        FC a2[4];
        #pragma unroll
        for (int j = 0; j < 4; j++) wmma::fill_fragment(a2[j], 0.f);
        gemm_bf3(a2, Ahi, Alo, Bhi, Blo, wr, wc);
        #pragma unroll
        for (int j = 0; j < 4; j++)
            wmma::store_matrix_sync(g_v + (size_t)(row0 + wr * 16) * H + wc * 64 + j * 16,
                                    a2[j], H, wmma::mem_row_major);
    }
}

// ---------------- edge: hsum[n] = sum_{s in seg(n)} gelu(u[s]+v[n]+b1) ----------------
__global__ void k_edge(const float* __restrict__ eb1) {
    int w = (blockIdx.x * blockDim.x + threadIdx.x) >> 5;
    int lane = threadIdx.x & 31;
    if (w >= NPAD) return;
    if (w >= NN) {
        ((float4*)(g_hsum + (size_t)w * H))[lane] = make_float4(0.f, 0.f, 0.f, 0.f);
        return;
    }
    float4 vv = ((const float4*)(g_v + (size_t)w * H))[lane];
    float4 bb = ((const float4*)eb1)[lane];
    vv.x += bb.x; vv.y += bb.y; vv.z += bb.z; vv.w += bb.w;
    float4 acc = make_float4(0.f, 0.f, 0.f, 0.f);
    int p  = g_rowptr[w];
    int p1 = g_rowptr[w + 1];
    for (; p + 2 <= p1; p += 2) {
        int s0 = g_srcs[p], s1 = g_srcs[p + 1];
        float4 u0 = ((const float4*)(g_u + (size_t)s0 * H))[lane];
        float4 u1 = ((const float4*)(g_u + (size_t)s1 * H))[lane];
        acc.x += gelu_f(u0.x + vv.x) + gelu_f(u1.x + vv.x);
        acc.y += gelu_f(u0.y + vv.y) + gelu_f(u1.y + vv.y);
        acc.z += gelu_f(u0.z + vv.z) + gelu_f(u1.z + vv.z);
        acc.w += gelu_f(u0.w + vv.w) + gelu_f(u1.w + vv.w);
    }
    if (p < p1) {
        int s0 = g_srcs[p];
        float4 u0 = ((const float4*)(g_u + (size_t)s0 * H))[lane];
        acc.x += gelu_f(u0.x + vv.x);
        acc.y += gelu_f(u0.y + vv.y);
        acc.z += gelu_f(u0.z + vv.z);
        acc.w += gelu_f(u0.w + vv.w);
    }
    ((float4*)(g_hsum + (size_t)w * H))[lane] = acc;
}

// ---------------- fused per-layer node kernel (BM=128) ----------------
// t = h@nW1a + hsum@Wcomb; G = gelu(t + deg*bcomb + nb1); upd = G@nW2;
// hnew = h + upd + nb2 -> g_h; then u,v = hnew@eW1(next) OR decode -> out.
__global__ __launch_bounds__(256) void k_p2(
    int l, const float* __restrict__ nb1, const float* __restrict__ nb2,
    int w_nW1a, int w_nW2, int w_comb, int w_uv_next,
    const float* __restrict__ db1, const float* __restrict__ dW2,
    const float* __restrict__ db2, float* __restrict__ out) {
    extern __shared__ char smc[];
    bf* Ahi = (bf*)smc;                     // 128 x LDB
    bf* Alo = Ahi + 128 * LDB;
    bf* Bhi = Alo + 128 * LDB;
    bf* Blo = Bhi + 128 * LDB;
    float* Cs  = (float*)(Blo + 128 * LDB); // 128 x LDC
    float* W2s = Cs + 128 * LDC;            // 128 x 8
    int tid = threadIdx.x, wid = tid >> 5, wr = wid >> 1, wc = wid & 1;
    int row0 = blockIdx.x * 128;

    loadsplit_A<128>(Ahi, Alo, g_h + (size_t)row0 * H, tid);
    copy_Bw(Bhi, Blo, w_nW1a, tid);
    __syncthreads();
    FC acc[2][4];
    fill0(acc);
    gemm128(acc, Ahi, Alo, Bhi, Blo, wr, wc);
    __syncthreads();
    loadsplit_A<128>(Ahi, Alo, g_hsum + (size_t)row0 * H, tid);
    copy_Bw(Bhi, Blo, w_comb, tid);
    __syncthreads();
    gemm128(acc, Ahi, Alo, Bhi, Blo, wr, wc);
    store128s(Cs, acc, wr, wc);
    __syncthreads();
    // G = gelu(t + deg*bcomb + nb1); split -> A
    for (int i = tid; i < 128 * 32; i += 256) {
        int r = i >> 5, c4 = (i & 31) << 2;
        int n = row0 + r;
        float d = (n < NN) ? (float)(g_rowptr[n + 1] - g_rowptr[n]) : 0.f;
        float4 v  = *(float4*)(Cs + r * LDC + c4);
        float4 bc = *(const float4*)(g_bcomb + l * H + c4);
        float4 b1 = *(const float4*)(nb1 + c4);
        v.x = gelu_f(v.x + d * bc.x + b1.x);
        v.y = gelu_f(v.y + d * bc.y + b1.y);
        v.z = gelu_f(v.z + d * bc.z + b1.z);
        v.w = gelu_f(v.w + d * bc.w + b1.w);
        split_smem4(Ahi, Alo, r * LDB + c4, v);
    }
    copy_Bw(Bhi, Blo, w_nW2, tid);
    __syncthreads();
    fill0(acc);
    gemm128(acc, Ahi, Alo, Bhi, Blo, wr, wc);
    store128s(Cs, acc, wr, wc);
    __syncthreads();
    // hnew = h + upd + nb2 -> g_h; split -> A
    for (int i = tid; i < 128 * 32; i += 256) {
        int r = i >> 5, c4 = (i & 31) << 2;
        size_t off = (size_t)(row0 + r) * H + c4;
        float4 v  = *(float4*)(Cs + r * LDC + c4);
        float4 ho = *(const float4*)(g_h + off);
        float4 b2 = *(const float4*)(nb2 + c4);
        v.x += ho.x + b2.x; v.y += ho.y + b2.y;
        v.z += ho.z + b2.z; v.w += ho.w + b2.w;
        *(float4*)(g_h + off) = v;
        split_smem4(Ahi, Alo, r * LDB + c4, v);
    }
    __syncthreads();

    if (w_uv_next >= 0) {
        copy_Bw(Bhi, Blo, w_uv_next, tid);
        __syncthreads();
        fill0(acc);
        gemm128(acc, Ahi, Alo, Bhi, Blo, wr, wc);
        store128g(g_u, row0, acc, wr, wc);
        __syncthreads();
        copy_Bw(Bhi, Blo, w_uv_next + 1, tid);
        __syncthreads();
        fill0(acc);
        gemm128(acc, Ahi, Alo, Bhi, Blo, wr, wc);
        store128g(g_v, row0, acc, wr, wc);
    } else {
        // decode: hid = gelu(hnew@dW1 + db1); out = hid@dW2 + db2 (exact SIMT tail)
        copy_Bw(Bhi, Blo, W_DECW1, tid);
        for (int i = tid; i < H * DOUT / 4; i += 256)
            *(float4*)(W2s + i * 4) = *(const float4*)(dW2 + i * 4);
        __syncthreads();
        fill0(acc);
        gemm128(acc, Ahi, Alo, Bhi, Blo, wr, wc);
        store128s(Cs, acc, wr, wc);
        __syncthreads();
        for (int i = tid; i < 128 * H; i += 256) {
            int r = i >> 7, c = i & 127;
            Cs[r * LDC + c] = gelu_f(Cs[r * LDC + c] + __ldg(db1 + c));
        }
        __syncthreads();
        for (int i = tid; i < 128 * DOUT; i += 256) {
            int r = i >> 3, o = i & 7;
            int n = row0 + r;
            if (n >= NN) continue;
            float a = __ldg(db2 + o);
            #pragma unroll 16
            for (int k = 0; k < H; k++) a += Cs[r * LDC + k] * W2s[k * DOUT + o];
            out[n * DOUT + o] = a;
        }
    }
}

// ---------------- launch ----------------
#define ENC_SMEM  ((64*DIN + DIN*H + 64*LDC) * 4 + (2*64 + 2*128) * LDB * 2)
#define P2_SMEM   (4 * 128 * LDB * 2 + 128 * LDC * 4 + H * DOUT * 4)
#define COMB_SMEM (2 * 16384 * 4)

extern "C" void kernel_launch(void* const* d_in, const int* in_sizes, int n_in,
                              void* d_out, int out_size) {
    const float* x     = (const float*)d_in[0];
    const int*   ei    = (const int*)d_in[1];
    const float* encW1 = (const float*)d_in[2];
    const float* encb1 = (const float*)d_in[3];
    const float* encW2 = (const float*)d_in[4];
    const float* encb2 = (const float*)d_in[5];
    const float* eW1   = (const float*)d_in[6];
    const float* eb1   = (const float*)d_in[7];
    const float* eW2   = (const float*)d_in[8];
    const float* eb2   = (const float*)d_in[9];
    const float* nW1   = (const float*)d_in[10];
    const float* nb1   = (const float*)d_in[11];
    const float* nW2   = (const float*)d_in[12];
    const float* nb2   = (const float*)d_in[13];
    const float* dW1   = (const float*)d_in[14];
    const float* db1   = (const float*)d_in[15];
    const float* dW2   = (const float*)d_in[16];
    const float* db2   = (const float*)d_in[17];
    float* out = (float*)d_out;

    cudaFuncSetAttribute(k_encode, cudaFuncAttributeMaxDynamicSharedMemorySize, ENC_SMEM);
    cudaFuncSetAttribute(k_p2,     cudaFuncAttributeMaxDynamicSharedMemorySize, P2_SMEM);
    cudaFuncSetAttribute(k_comb,   cudaFuncAttributeMaxDynamicSharedMemorySize, COMB_SMEM);

    const int* src = ei;
    const int* dst = ei + NE;

    void* tmpp = nullptr;
    cudaGetSymbolAddress(&tmpp, g_tmp);

    cudaMemsetAsync(tmpp, 0, NN * sizeof(int));
    k_count<<<(NE + 255) / 256, 256>>>(dst);
    k_scan<<<1, 1024>>>();
    cudaMemsetAsync(tmpp, 0, NN * sizeof(int));
    k_fill<<<(NE + 255) / 256, 256>>>(src, dst);

    WSrc ws{encW2, eW1, nW1, nW2, dW1};
    k_split_w<<<(NW_SPLIT * 16384 + 255) / 256, 256>>>(ws);

    k_encode<<<NPAD / 64, 256, ENC_SMEM>>>(x, encW1, encb1, encb2);

    for (int l = 0; l < NL; l++) {
        k_edge<<<NPAD / 8, 256>>>(eb1 + (size_t)l * H);
        if (l == 0) k_comb<<<NL, 256, COMB_SMEM>>>(eW2, nW1, eb2);
        bool last = (l == NL - 1);
        k_p2<<<NPAD / 128, 256, P2_SMEM>>>(
            l, nb1 + (size_t)l * H, nb2 + (size_t)l * H,
            W_NW1A(l), W_NW2(l), W_COMB(l),
            last ? -1 : W_EW1(l + 1, 0),
            db1, dW2, db2, out);
    }
}